// round 15
// baseline (speedup 1.0000x reference)
#include <cuda_runtime.h>
#include <cuda_fp16.h>
#include <math_constants.h>
#include <cstdint>

#define NN 10000
#define EE 160000
#define EDIM 32
#define HID 128
#define NH 4
#define TM 64             // edges per block
#define THREADS 256

// ---------------- scratch (static device arrays; no allocation) ----------------
__device__ __half g_wthi[2 * 512 * 128];  // [conv][n][k] fp16 of [wl|wr]^T
__device__ __half g_w1hi[2 * 128 * 32];   // [conv][j][i] fp16 of w1^T
__device__ float g_bias[2][512];          // [conv][bl(256)|br(256)]
__device__ float g_q[NN * 64];
__device__ float g_den[NN * NH];

__device__ __forceinline__ uint32_t smem_to_u32(const void* p) {
    uint32_t a;
    asm("{ .reg .u64 t; cvta.to.shared.u64 t, %1; cvt.u32.u64 %0, t; }" : "=r"(a) : "l"(p));
    return a;
}
__device__ __forceinline__ void ldsm4(uint32_t a, uint32_t* r) {
    asm volatile("ldmatrix.sync.aligned.m8n8.x4.shared.b16 {%0,%1,%2,%3}, [%4];"
                 : "=r"(r[0]), "=r"(r[1]), "=r"(r[2]), "=r"(r[3]) : "r"(a));
}
__device__ __forceinline__ void mma16816(float* c, const uint32_t* a, const uint32_t* b) {
    asm volatile("mma.sync.aligned.m16n8k16.row.col.f32.f16.f16.f32 "
                 "{%0,%1,%2,%3}, {%4,%5,%6,%7}, {%8,%9}, {%0,%1,%2,%3};"
                 : "+f"(c[0]), "+f"(c[1]), "+f"(c[2]), "+f"(c[3])
                 : "r"(a[0]), "r"(a[1]), "r"(a[2]), "r"(a[3]), "r"(b[0]), "r"(b[1]));
}
__device__ __forceinline__ void cp16(uint32_t dst, const void* src) {
    asm volatile("cp.async.cg.shared.global [%0], [%1], 16;" :: "r"(dst), "l"(src) : "memory");
}

// ---------------- kernel 0: pre-convert weights (fp16, transposed) ----------------
__global__ void presplit_kernel(const float* __restrict__ kwl, const float* __restrict__ kwr,
                                const float* __restrict__ vwl, const float* __restrict__ vwr,
                                const float* __restrict__ kbl, const float* __restrict__ kbr,
                                const float* __restrict__ vbl, const float* __restrict__ vbr,
                                const float* __restrict__ kw1, const float* __restrict__ vw1) {
    int idx = blockIdx.x * blockDim.x + threadIdx.x;   // 131072
    if (idx < 2 * 512 * 128) {
        int conv = idx >> 16;
        int rem = idx & 65535;
        int n = rem >> 7, k = rem & 127;
        const float* w = conv ? (n < 256 ? vwl : vwr) : (n < 256 ? kwl : kwr);
        g_wthi[idx] = __float2half_rn(w[k * 256 + (n & 255)]);
    }
    if (idx < 2 * 128 * 32) {
        int conv = idx >> 12;
        int rem = idx & 4095;
        int j = rem >> 5, i = rem & 31;
        g_w1hi[idx] = __float2half_rn((conv ? vw1 : kw1)[i * 128 + j]);
    }
    if (idx < 1024) {
        int conv = idx >> 9, j = idx & 511;
        const float* s = conv ? (j < 256 ? vbl : vbr) : (j < 256 ? kbl : kbr);
        g_bias[conv][j] = s[j & 255];
    }
}

// ---------------- kernel 1: Q equivariant linear + init ----------------
__global__ void qinit_kernel(const float* __restrict__ f,
                             const float* __restrict__ qw,
                             const float* __restrict__ qb,
                             float* __restrict__ dout) {
    int p = blockIdx.x * blockDim.x + threadIdx.x;
    if (p < NN * 64) {
        int n = p >> 6, j = p & 63;
        int o = j >> 2, d = j & 3;
        int l = (d == 0) ? 0 : 1;
        float acc = (d == 0) ? qb[o] : 0.f;
        const float* wrow = qw + (l * 16 + o) * 16;
        const float* frow = f + n * 64 + d;
#pragma unroll
        for (int m = 0; m < 16; m++) acc += wrow[m] * frow[m * 4];
        g_q[p] = acc;
        dout[p] = 0.f;
    }
    if (p < NN * NH) g_den[p] = 0.f;
}

// ---------------- kernel 2: fused K+V conv (TM=64, occ 2) ----------------
// smem byte offsets
#define OFF_A    0u         // 16384: 64e x 128k fp16 A tile
#define OFF_W    16384u     // 65536: one W half; after pass L: t2 @+0 (8448), b2 @+8448 (2048)
#define OFF_T    81920u     // 8448: t (NOT aliased — survives both convs)
#define OFF_RT   90368u     // 2048
#define OFF_BIAS 92416u     // 2048
#define OFF_EF   94464u     // 8192: ef fp16 tile (survives both convs)
#define OFF_W1T  102656u    // 8192
#define OFF_EX   110848u    // 1024: ex[64][4] (K -> V)
#define SMEM_BYTES 111872u

__device__ __forceinline__ void load_whalf(uint32_t smem_base, int conv, int nbase, int tid) {
#pragma unroll
    for (int ii = 0; ii < 16; ii++) {
        int g = ii * THREADS + tid;             // 0..4095 16B-chunks (256 rows x 16)
        int n = g >> 4, q = g & 15;
        const __half* src = g_wthi + conv * 65536 + (nbase + n) * 128 + q * 8;
        uint32_t dst = smem_base + OFF_W + (uint32_t)(n * 256 + ((q ^ (n & 7)) << 4));
        cp16(dst, src);
    }
    asm volatile("cp.async.commit_group;" ::: "memory");
}
__device__ __forceinline__ void load_w1t(uint32_t smem_base, int conv, int tid) {
#pragma unroll
    for (int r = 0; r < 2; r++) {
        int g = r * THREADS + tid;              // 512 chunks (128 rows x 4)
        int n = g >> 2, q = g & 3;
        const __half* srcp = g_w1hi + conv * 4096 + n * 32 + q * 8;
        uint32_t dstp = smem_base + OFF_W1T + (uint32_t)(n * 64 + ((q ^ (n & 3)) << 4));
        cp16(dstp, srcp);
    }
    asm volatile("cp.async.commit_group;" ::: "memory");
}

__global__ void __launch_bounds__(THREADS, 2)
conv_fused_kernel(const float* __restrict__ basis1, const float* __restrict__ basis2,
                  const float* __restrict__ ef, const float* __restrict__ f,
                  const int* __restrict__ src, const int* __restrict__ dst,
                  const float* __restrict__ k_b1, const float* __restrict__ v_b1,
                  float* __restrict__ dout) {
    extern __shared__ char sm[];
    const uint32_t smem_base = smem_to_u32(sm);
    const int tid = threadIdx.x;
    const int lane = tid & 31, wid = tid >> 5;
    const int l4 = lane & 3;
    const int ng = wid;                         // 0..7
    const int e0 = blockIdx.x * TM;

    float* sh_t   = (float*)(sm + OFF_T);
    float* sh_rt  = (float*)(sm + OFF_RT);
    float* sh_bias= (float*)(sm + OFF_BIAS);
    float* sh_t2  = (float*)(sm + OFF_W);       // valid only after pass-L barrier
    float* sh_b2  = (float*)(sm + OFF_W + 8448u);
    float* sh_ex  = (float*)(sm + OFF_EX);

    const int a_row_off = ((lane >> 3) & 1) * 8 + (lane & 7);
    const int a_ksel = (lane >> 4) & 1;
    const int b_n_off = ((lane >> 4) & 1) * 8 + (lane & 7);
    const int b_ksel = (lane >> 3) & 1;

    // ---- one-time staging: prefetch K weights; ef + t ----
    load_w1t(smem_base, 0, tid);
    load_whalf(smem_base, 0, 256, tid);
#pragma unroll
    for (int r = 0; r < 2; r++) {
        int idx = r * THREADS + tid;            // 512 float4s (64e x 8)
        int e = idx >> 3, i0 = (idx & 7) * 4;
        float4 v = ((const float4*)(ef + (size_t)e0 * EDIM))[idx];
        __half2 h01 = __floats2half2_rn(v.x, v.y);
        __half2 h23 = __floats2half2_rn(v.z, v.w);
        int q = i0 >> 3;
        uint32_t base = (uint32_t)(e * 128 + ((q ^ (e & 7)) << 4) + (i0 & 7) * 2);
        *(uint32_t*)(sm + OFF_EF + base)     = *reinterpret_cast<uint32_t*>(&h01);
        *(uint32_t*)(sm + OFF_EF + base + 4) = *reinterpret_cast<uint32_t*>(&h23);
    }
#pragma unroll
    for (int r = 0; r < 4; r++) {               // 1024 (e,m) pairs — gather halved
        int p = r * THREADS + tid;
        int e = p >> 4, m = p & 15;
        int sn = __ldg(&src[e0 + e]);
        float4 fv = *reinterpret_cast<const float4*>(f + (size_t)sn * 64 + m * 4);
        float4 b1a = *reinterpret_cast<const float4*>(basis1 + (size_t)(e0 + e) * 8);
        float4 b1b = *reinterpret_cast<const float4*>(basis1 + (size_t)(e0 + e) * 8 + 4);
        sh_t[e * 33 + 2 * m]     = fv.x * b1a.x + fv.y * b1a.z + fv.z * b1b.x + fv.w * b1b.z;
        sh_t[e * 33 + 2 * m + 1] = fv.x * b1a.y + fv.y * b1a.w + fv.z * b1b.y + fv.w * b1b.w;
    }

#pragma unroll 1
    for (int conv = 0; conv < 2; conv++) {
        const float* hbv = conv ? v_b1 : k_b1;
        // bias for this conv
        sh_bias[tid] = g_bias[conv][tid];
        sh_bias[256 + tid] = g_bias[conv][256 + tid];
        asm volatile("cp.async.wait_group 1;" ::: "memory");   // w1t resident
        __syncthreads();                                        // ef/t/bias visible

        // ---- h-phase: h = gelu(ef @ w1 + b1) -> fp16 A tile ----
        {
            const int wj = wid * 16;
            float bj[2][2];
#pragma unroll
            for (int nt = 0; nt < 2; nt++) {
                int j0 = wj + nt * 8 + 2 * l4;
                bj[nt][0] = __ldg(&hbv[j0]);
                bj[nt][1] = __ldg(&hbv[j0 + 1]);
            }
            uint32_t Bh[2][4];
#pragma unroll
            for (int kc = 0; kc < 2; kc++) {
                int n = wj + b_n_off;
                int c = kc * 2 + b_ksel;
                uint32_t bd = smem_base + OFF_W1T + (uint32_t)(n * 64 + ((c ^ (n & 3)) << 4));
                ldsm4(bd, Bh[kc]);
            }
#pragma unroll
            for (int mt = 0; mt < 4; mt++) {
                float hacc[2][4];
#pragma unroll
                for (int nt = 0; nt < 2; nt++)
#pragma unroll
                    for (int u = 0; u < 4; u++) hacc[nt][u] = 0.f;
#pragma unroll
                for (int kc = 0; kc < 2; kc++) {
                    int arow = mt * 16 + a_row_off;
                    int c = kc * 2 + a_ksel;
                    uint32_t ad = smem_base + OFF_EF + (uint32_t)(arow * 128 + ((c ^ (arow & 7)) << 4));
                    uint32_t Ah[4];
                    ldsm4(ad, Ah);
#pragma unroll
                    for (int nt = 0; nt < 2; nt++)
                        mma16816(hacc[nt], Ah, &Bh[kc][nt * 2]);
                }
#pragma unroll
                for (int nt = 0; nt < 2; nt++) {
                    int j0 = wj + nt * 8 + 2 * l4;
                    int jc = j0 >> 3;
#pragma unroll
                    for (int hrow = 0; hrow < 2; hrow++) {
                        int e = mt * 16 + hrow * 8 + (lane >> 2);
                        float v0 = hacc[nt][hrow * 2]     + bj[nt][0];
                        float v1 = hacc[nt][hrow * 2 + 1] + bj[nt][1];
                        v0 = v0 * normcdff(v0);
                        v1 = v1 * normcdff(v1);
                        __half2 hp = __floats2half2_rn(v0, v1);
                        uint32_t addr = (uint32_t)(e * 256 + ((jc ^ (e & 7)) << 4) + (j0 & 7) * 2);
                        *(uint32_t*)(sm + OFF_A + addr) = *reinterpret_cast<uint32_t*>(&hp);
                    }
                }
            }
        }
        asm volatile("cp.async.wait_group 0;" ::: "memory");   // right W half resident
        __syncthreads();                                       // A tile visible

        // ================= PASS R (W rows 256..511) =================
        {
            float acc[4][4][4];
#pragma unroll
            for (int mt = 0; mt < 4; mt++)
#pragma unroll
                for (int nt = 0; nt < 4; nt++)
#pragma unroll
                    for (int u = 0; u < 4; u++) acc[mt][nt][u] = 0.f;
#pragma unroll
            for (int ks = 0; ks < 8; ks++) {
                uint32_t A[4][4];
#pragma unroll
                for (int mt = 0; mt < 4; mt++) {
                    int arow = mt * 16 + a_row_off;
                    int kc = ks * 2 + a_ksel;
                    ldsm4(smem_base + OFF_A + (uint32_t)(arow * 256 + ((kc ^ (arow & 7)) << 4)), A[mt]);
                }
#pragma unroll
                for (int g2 = 0; g2 < 2; g2++) {
                    int n = ng * 32 + g2 * 16 + b_n_off;
                    int kc = ks * 2 + b_ksel;
                    uint32_t Bhi[4];
                    ldsm4(smem_base + OFF_W + (uint32_t)(n * 256 + ((kc ^ (n & 7)) << 4)), Bhi);
#pragma unroll
                    for (int mt = 0; mt < 4; mt++) {
                        mma16816(acc[mt][g2 * 2],     A[mt], &Bhi[0]);
                        mma16816(acc[mt][g2 * 2 + 1], A[mt], &Bhi[2]);
                    }
                }
            }
            __syncthreads();                        // done reading right W
            load_whalf(smem_base, conv, 0, tid);    // prefetch left half

            // right epilogue: rt[e][ng]
#pragma unroll
            for (int mt = 0; mt < 4; mt++)
#pragma unroll
                for (int h2 = 0; h2 < 2; h2++) {
                    int e = mt * 16 + h2 * 8 + (lane >> 2);
                    float s = 0.f;
#pragma unroll
                    for (int nt = 0; nt < 4; nt++) {
                        int nc = nt * 8 + 2 * l4;
                        int o = 256 + ng * 32 + nc;
                        s += (acc[mt][nt][h2 * 2] + sh_bias[o]) * sh_t[e * 33 + nc]
                           + (acc[mt][nt][h2 * 2 + 1] + sh_bias[o + 1]) * sh_t[e * 33 + nc + 1];
                    }
                    s += __shfl_xor_sync(0xFFFFFFFFu, s, 1);
                    s += __shfl_xor_sync(0xFFFFFFFFu, s, 2);
                    if (l4 == 0) sh_rt[e * 8 + ng] = s;
                }
        }
        asm volatile("cp.async.wait_group 0;" ::: "memory");   // left W half resident
        __syncthreads();                                       // rt visible

        // ================= PASS L (W rows 0..255) =================
        float accL[4][4][4];
        {
#pragma unroll
            for (int mt = 0; mt < 4; mt++)
#pragma unroll
                for (int nt = 0; nt < 4; nt++)
#pragma unroll
                    for (int u = 0; u < 4; u++) accL[mt][nt][u] = 0.f;
#pragma unroll
            for (int ks = 0; ks < 8; ks++) {
                uint32_t A[4][4];
#pragma unroll
                for (int mt = 0; mt < 4; mt++) {
                    int arow = mt * 16 + a_row_off;
                    int kc = ks * 2 + a_ksel;
                    ldsm4(smem_base + OFF_A + (uint32_t)(arow * 256 + ((kc ^ (arow & 7)) << 4)), A[mt]);
                }
#pragma unroll
                for (int g2 = 0; g2 < 2; g2++) {
                    int n = ng * 32 + g2 * 16 + b_n_off;
                    int kc = ks * 2 + b_ksel;
                    uint32_t Bhi[4];
                    ldsm4(smem_base + OFF_W + (uint32_t)(n * 256 + ((kc ^ (n & 7)) << 4)), Bhi);
#pragma unroll
                    for (int mt = 0; mt < 4; mt++) {
                        mma16816(accL[mt][g2 * 2],     A[mt], &Bhi[0]);
                        mma16816(accL[mt][g2 * 2 + 1], A[mt], &Bhi[2]);
                    }
                }
            }
        }
        __syncthreads();                            // all mma done -> W region now free

        // left epilogue: t2 -> W region; stage b2 alongside
        if (tid < 128) {
            ((float4*)sh_b2)[tid] = ((const float4*)(basis2 + (size_t)e0 * 8))[tid];
        }
#pragma unroll
        for (int mt = 0; mt < 4; mt++)
#pragma unroll
            for (int h2 = 0; h2 < 2; h2++) {
                int e = mt * 16 + h2 * 8 + (lane >> 2);
                float r0 = sh_rt[e * 8 + 2 * l4];
                float r1 = sh_rt[e * 8 + 2 * l4 + 1];
#pragma unroll
                for (int nt = 0; nt < 4; nt++) {
                    int o = ng * 32 + nt * 8 + 2 * l4;
                    float s = (accL[mt][nt][h2 * 2] + sh_bias[o]) * r0
                            + (accL[mt][nt][h2 * 2 + 1] + sh_bias[o + 1]) * r1;
                    s += __shfl_xor_sync(0xFFFFFFFFu, s, 1);
                    s += __shfl_xor_sync(0xFFFFFFFFu, s, 2);
                    if (l4 == 0)
                        sh_t2[e * 33 + ng * 4 + nt] = s;
                }
            }
        __syncthreads();                            // t2 + b2 visible

        // ---- per-conv final ----
        if (conv == 0) {
            // K: scores -> ex (smem) + segment denominator
            int e = tid >> 2, hh = tid & 3;
            int dn = __ldg(&dst[e0 + e]);
            const float* qr = g_q + dn * 64 + hh * 16;
            float s = 0.f;
#pragma unroll
            for (int m = hh * 4; m < hh * 4 + 4; m++) {
                float ta = sh_t2[e * 33 + 2 * m];
                float tb = sh_t2[e * 33 + 2 * m + 1];
#pragma unroll
                for (int d = 0; d < 4; d++) {
                    float kv = ta * sh_b2[e * 8 + d] + tb * sh_b2[e * 8 + 4 + d];
                    s += qr[(m - hh * 4) * 4 + d] * kv;
                }
            }
            float ex = expf(s * 0.25f);
            sh_ex[e * 4 + hh] = ex;
            atomicAdd(&g_den[dn * NH + hh], ex);
            __syncthreads();                        // K-final done before V overwrites W/A
        } else {
            // V: numerator scatter — ex * v straight to dout via red.v4
#pragma unroll
            for (int r = 0; r < 4; r++) {
                int p = r * THREADS + tid;          // 1024 (e,m) float4 groups
                int e = p >> 4, m = p & 15;
                int hh = m >> 2;
                int dn = __ldg(&dst[e0 + e]);
                float ta = sh_t2[e * 33 + 2 * m];
                float tb = sh_t2[e * 33 + 2 * m + 1];
                float ex = sh_ex[e * 4 + hh];
                float* op = dout + (size_t)dn * 64 + m * 4;
                asm volatile("red.global.add.v4.f32 [%0], {%1, %2, %3, %4};"
                             :: "l"(op),
                                "f"(ex * (ta * sh_b2[e * 8 + 0] + tb * sh_b2[e * 8 + 4])),
                                "f"(ex * (ta * sh_b2[e * 8 + 1] + tb * sh_b2[e * 8 + 5])),
                                "f"(ex * (ta * sh_b2[e * 8 + 2] + tb * sh_b2[e * 8 + 6])),
                                "f"(ex * (ta * sh_b2[e * 8 + 3] + tb * sh_b2[e * 8 + 7]))
                             : "memory");
            }
        }
        if (conv == 0) {
            // prefetch V weights for next iteration (after K-final barrier)
            load_w1t(smem_base, 1, tid);
            load_whalf(smem_base, 1, 256, tid);
        }
    }
}

// ---------------- kernel 3: divide numerators by segment denominator ----------------
__global__ void divide_kernel(float* __restrict__ dout) {
    int p = blockIdx.x * blockDim.x + threadIdx.x;
    if (p >= NN * 64) return;
    int n = p >> 6, hh = (p & 63) >> 4;
    dout[p] /= fmaxf(g_den[n * NH + hh], 1e-9f);
}

// ---------------- launch ----------------
extern "C" void kernel_launch(void* const* d_in, const int* in_sizes, int n_in,
                              void* d_out, int out_size) {
    const float* basis1 = (const float*)d_in[0];
    const float* basis2 = (const float*)d_in[1];
    const float* ef     = (const float*)d_in[2];
    const float* f      = (const float*)d_in[3];
    const int*   src    = (const int*)d_in[4];
    const int*   dst    = (const int*)d_in[5];
    const float* q_w    = (const float*)d_in[6];
    const float* q_b    = (const float*)d_in[7];
    const float* k_w1   = (const float*)d_in[8];
    const float* k_b1   = (const float*)d_in[9];
    const float* k_wl   = (const float*)d_in[10];
    const float* k_bl   = (const float*)d_in[11];
    const float* k_wr   = (const float*)d_in[12];
    const float* k_br   = (const float*)d_in[13];
    const float* v_w1   = (const float*)d_in[14];
    const float* v_b1   = (const float*)d_in[15];
    const float* v_wl   = (const float*)d_in[16];
    const float* v_bl   = (const float*)d_in[17];
    const float* v_wr   = (const float*)d_in[18];
    const float* v_br   = (const float*)d_in[19];
    float* dout = (float*)d_out;

    cudaFuncSetAttribute(conv_fused_kernel, cudaFuncAttributeMaxDynamicSharedMemorySize, SMEM_BYTES);

    presplit_kernel<<<512, 256>>>(k_wl, k_wr, v_wl, v_wr, k_bl, k_br, v_bl, v_br, k_w1, v_w1);
    qinit_kernel<<<(NN * 64 + 255) / 256, 256>>>(f, q_w, q_b, dout);
    conv_fused_kernel<<<EE / TM, THREADS, SMEM_BYTES>>>(
        basis1, basis2, ef, f, src, dst, k_b1, v_b1, dout);
    divide_kernel<<<(NN * 64 + 255) / 256, 256>>>(dout);
}

// round 16
// speedup vs baseline: 1.2750x; 1.2750x over previous
#include <cuda_runtime.h>
#include <cuda_fp16.h>
#include <math_constants.h>
#include <cstdint>

#define NN 10000
#define EE 160000
#define EDIM 32
#define HID 128
#define NH 4
#define TM 64             // edges per block
#define THREADS 256

// ---------------- scratch (static device arrays; no allocation) ----------------
__device__ __half g_wthi[2 * 512 * 128];  // [conv][n][k] fp16-hi of [wl|wr]^T
__device__ __half g_w1hi[2 * 128 * 32];   // [conv][j][i] fp16-hi of w1^T
__device__ float g_bias[2][512];          // [conv][bl(256)|br(256)]
__device__ float g_q[NN * 64];
__device__ float g_ex[EE * NH];
__device__ float g_den[NN * NH];

__device__ __forceinline__ uint32_t smem_to_u32(const void* p) {
    uint32_t a;
    asm("{ .reg .u64 t; cvta.to.shared.u64 t, %1; cvt.u32.u64 %0, t; }" : "=r"(a) : "l"(p));
    return a;
}
__device__ __forceinline__ void ldsm4(uint32_t a, uint32_t* r) {
    asm volatile("ldmatrix.sync.aligned.m8n8.x4.shared.b16 {%0,%1,%2,%3}, [%4];"
                 : "=r"(r[0]), "=r"(r[1]), "=r"(r[2]), "=r"(r[3]) : "r"(a));
}
__device__ __forceinline__ void mma16816(float* c, const uint32_t* a, const uint32_t* b) {
    asm volatile("mma.sync.aligned.m16n8k16.row.col.f32.f16.f16.f32 "
                 "{%0,%1,%2,%3}, {%4,%5,%6,%7}, {%8,%9}, {%0,%1,%2,%3};"
                 : "+f"(c[0]), "+f"(c[1]), "+f"(c[2]), "+f"(c[3])
                 : "r"(a[0]), "r"(a[1]), "r"(a[2]), "r"(a[3]), "r"(b[0]), "r"(b[1]));
}
__device__ __forceinline__ void cp16(uint32_t dst, const void* src) {
    asm volatile("cp.async.cg.shared.global [%0], [%1], 16;" :: "r"(dst), "l"(src) : "memory");
}

// ---------------- kernel 0: pre-convert weights (fp16, transposed) ----------------
__global__ void presplit_kernel(const float* __restrict__ kwl, const float* __restrict__ kwr,
                                const float* __restrict__ vwl, const float* __restrict__ vwr,
                                const float* __restrict__ kbl, const float* __restrict__ kbr,
                                const float* __restrict__ vbl, const float* __restrict__ vbr,
                                const float* __restrict__ kw1, const float* __restrict__ vw1) {
    int idx = blockIdx.x * blockDim.x + threadIdx.x;   // 131072
    if (idx < 2 * 512 * 128) {
        int conv = idx >> 16;
        int rem = idx & 65535;
        int n = rem >> 7, k = rem & 127;
        const float* w = conv ? (n < 256 ? vwl : vwr) : (n < 256 ? kwl : kwr);
        g_wthi[idx] = __float2half_rn(w[k * 256 + (n & 255)]);
    }
    if (idx < 2 * 128 * 32) {                          // w1^T (hi only)
        int conv = idx >> 12;
        int rem = idx & 4095;
        int j = rem >> 5, i = rem & 31;
        g_w1hi[idx] = __float2half_rn((conv ? vw1 : kw1)[i * 128 + j]);
    }
    if (idx < 1024) {
        int conv = idx >> 9, j = idx & 511;
        const float* s = conv ? (j < 256 ? vbl : vbr) : (j < 256 ? kbl : kbr);
        g_bias[conv][j] = s[j & 255];
    }
}

// ---------------- kernel 1: Q equivariant linear + init ----------------
__global__ void qinit_kernel(const float* __restrict__ f,
                             const float* __restrict__ qw,
                             const float* __restrict__ qb,
                             float* __restrict__ dout) {
    int p = blockIdx.x * blockDim.x + threadIdx.x;
    if (p < NN * 64) {
        int n = p >> 6, j = p & 63;
        int o = j >> 2, d = j & 3;
        int l = (d == 0) ? 0 : 1;
        float acc = (d == 0) ? qb[o] : 0.f;
        const float* wrow = qw + (l * 16 + o) * 16;
        const float* frow = f + n * 64 + d;
#pragma unroll
        for (int m = 0; m < 16; m++) acc += wrow[m] * frow[m * 4];
        g_q[p] = acc;
        dout[p] = 0.f;
    }
    if (p < NN * NH) g_den[p] = 0.f;
}

// ---------------- kernel 2: mma.sync fused conv (TM=64, occ 2) ----------------
// smem byte offsets
#define OFF_A    0u         // 16384: 64e x 128k fp16 (256B rows, swizzled)
#define OFF_W    16384u     // 65536: one W half (256 n-rows x 256B)
#define OFF_T    81920u     // 64*33*4 = 8448 (t; aliased as t2)
#define OFF_RT   90368u     // 64*8*4 = 2048 (reused as dn[] in V final)
#define OFF_BIAS 92416u     // 512*4 (reused as alpha in V final)
#define OFF_EF   94464u     // 8192: 64e x 128B (fp16 ef rows, swizzled)
#define OFF_W1T  102656u    // 8192: w1t hi
#define SMEM_BYTES 110848u

__device__ __forceinline__ void load_whalf(uint32_t smem_base, int conv, int nbase, int tid) {
#pragma unroll
    for (int ii = 0; ii < 16; ii++) {
        int g = ii * THREADS + tid;             // 0..4095 16B-chunks (256 rows x 16)
        int n = g >> 4, q = g & 15;
        const __half* src = g_wthi + conv * 65536 + (nbase + n) * 128 + q * 8;
        uint32_t dst = smem_base + OFF_W + (uint32_t)(n * 256 + ((q ^ (n & 7)) << 4));
        cp16(dst, src);
    }
    asm volatile("cp.async.commit_group;" ::: "memory");
}

__global__ void __launch_bounds__(THREADS, 2)
conv_mma_kernel(const float* __restrict__ basis1, const float* __restrict__ basis2,
                const float* __restrict__ ef, const float* __restrict__ f,
                const int* __restrict__ src, const int* __restrict__ dst,
                const float* __restrict__ k_b1, const float* __restrict__ v_b1,
                float* __restrict__ dout, int conv) {
    extern __shared__ char sm[];
    const uint32_t smem_base = smem_to_u32(sm);
    const int tid = threadIdx.x;
    const int lane = tid & 31, wid = tid >> 5;
    const int l4 = lane & 3;
    const int ng = wid;                         // 0..7: n base = ng*32 (all warps share e 0..63)
    const int e0 = blockIdx.x * TM;

    float* sh_t   = (float*)(sm + OFF_T);       // later aliased as t2
    float* sh_rt  = (float*)(sm + OFF_RT);
    float* sh_bias= (float*)(sm + OFF_BIAS);

    const int a_row_off = ((lane >> 3) & 1) * 8 + (lane & 7);
    const int a_ksel = (lane >> 4) & 1;
    const int b_n_off = ((lane >> 4) & 1) * 8 + (lane & 7);
    const int b_ksel = (lane >> 3) & 1;

    // ---- prefetch: w1t hi (group0), right W half (group1) ----
#pragma unroll
    for (int r = 0; r < 2; r++) {
        int g = r * THREADS + tid;              // 512 chunks (128 rows x 4)
        int n = g >> 2, q = g & 3;
        const __half* srcp = g_w1hi + conv * 4096 + n * 32 + q * 8;
        uint32_t dstp = smem_base + OFF_W1T + (uint32_t)(n * 64 + ((q ^ (n & 3)) << 4));
        cp16(dstp, srcp);
    }
    asm volatile("cp.async.commit_group;" ::: "memory");
    load_whalf(smem_base, conv, 256, tid);

    // ---- stage ef (fp32 -> fp16 tile), bias; compute t ((e,m) granularity) ----
#pragma unroll
    for (int r = 0; r < 2; r++) {
        int idx = r * THREADS + tid;            // 512 float4s (64e x 8)
        int e = idx >> 3, i0 = (idx & 7) * 4;
        float4 v = ((const float4*)(ef + (size_t)e0 * EDIM))[idx];
        __half2 h01 = __floats2half2_rn(v.x, v.y);
        __half2 h23 = __floats2half2_rn(v.z, v.w);
        int q = i0 >> 3;
        uint32_t base = (uint32_t)(e * 128 + ((q ^ (e & 7)) << 4) + (i0 & 7) * 2);
        *(uint32_t*)(sm + OFF_EF + base)     = *reinterpret_cast<uint32_t*>(&h01);
        *(uint32_t*)(sm + OFF_EF + base + 4) = *reinterpret_cast<uint32_t*>(&h23);
    }
    sh_bias[tid] = g_bias[conv][tid];
    sh_bias[256 + tid] = g_bias[conv][256 + tid];
#pragma unroll
    for (int r = 0; r < 4; r++) {               // 1024 (e,m) pairs — gathers halved
        int p = r * THREADS + tid;
        int e = p >> 4, m = p & 15;
        int sn = __ldg(&src[e0 + e]);
        float4 fv = *reinterpret_cast<const float4*>(f + (size_t)sn * 64 + m * 4);
        float4 b1a = *reinterpret_cast<const float4*>(basis1 + (size_t)(e0 + e) * 8);
        float4 b1b = *reinterpret_cast<const float4*>(basis1 + (size_t)(e0 + e) * 8 + 4);
        sh_t[e * 33 + 2 * m]     = fv.x * b1a.x + fv.y * b1a.z + fv.z * b1b.x + fv.w * b1b.z;
        sh_t[e * 33 + 2 * m + 1] = fv.x * b1a.y + fv.y * b1a.w + fv.z * b1b.y + fv.w * b1b.w;
    }
    asm volatile("cp.async.wait_group 1;" ::: "memory");   // w1t resident
    __syncthreads();                                       // ef/t visible

    // ---- h-phase on tensor cores: h = gelu(ef @ w1hi + b1) -> fp16 A tile ----
    {
        const float* hbv = conv ? v_b1 : k_b1;
        const int wj = wid * 16;                // j base 0..112
        float bj[2][2];
#pragma unroll
        for (int nt = 0; nt < 2; nt++) {
            int j0 = wj + nt * 8 + 2 * l4;
            bj[nt][0] = __ldg(&hbv[j0]);
            bj[nt][1] = __ldg(&hbv[j0 + 1]);
        }
        uint32_t Bh[2][4];
#pragma unroll
        for (int kc = 0; kc < 2; kc++) {
            int n = wj + b_n_off;
            int c = kc * 2 + b_ksel;
            uint32_t bd = smem_base + OFF_W1T + (uint32_t)(n * 64 + ((c ^ (n & 3)) << 4));
            ldsm4(bd, Bh[kc]);
        }
#pragma unroll
        for (int mt = 0; mt < 4; mt++) {
            float hacc[2][4];
#pragma unroll
            for (int nt = 0; nt < 2; nt++)
#pragma unroll
                for (int u = 0; u < 4; u++) hacc[nt][u] = 0.f;
#pragma unroll
            for (int kc = 0; kc < 2; kc++) {
                int arow = mt * 16 + a_row_off;
                int c = kc * 2 + a_ksel;
                uint32_t ad = smem_base + OFF_EF + (uint32_t)(arow * 128 + ((c ^ (arow & 7)) << 4));
                uint32_t Ah[4];
                ldsm4(ad, Ah);
#pragma unroll
                for (int nt = 0; nt < 2; nt++)
                    mma16816(hacc[nt], Ah, &Bh[kc][nt * 2]);
            }
#pragma unroll
            for (int nt = 0; nt < 2; nt++) {
                int j0 = wj + nt * 8 + 2 * l4;
                int jc = j0 >> 3;
#pragma unroll
                for (int hrow = 0; hrow < 2; hrow++) {
                    int e = mt * 16 + hrow * 8 + (lane >> 2);
                    float v0 = hacc[nt][hrow * 2]     + bj[nt][0];
                    float v1 = hacc[nt][hrow * 2 + 1] + bj[nt][1];
                    v0 = v0 * normcdff(v0);
                    v1 = v1 * normcdff(v1);
                    __half2 hp = __floats2half2_rn(v0, v1);
                    uint32_t addr = (uint32_t)(e * 256 + ((jc ^ (e & 7)) << 4) + (j0 & 7) * 2);
                    *(uint32_t*)(sm + OFF_A + addr) = *reinterpret_cast<uint32_t*>(&hp);
                }
            }
        }
    }
    asm volatile("cp.async.wait_group 0;" ::: "memory");   // right W half resident
    __syncthreads();                                       // A tile visible
    float* sh_t2 = sh_t;

    // ================= PASS R (W rows 256..511, buffer rows 0..255) =================
    {
        float acc[4][4][4];
#pragma unroll
        for (int mt = 0; mt < 4; mt++)
#pragma unroll
            for (int nt = 0; nt < 4; nt++)
#pragma unroll
                for (int u = 0; u < 4; u++) acc[mt][nt][u] = 0.f;
#pragma unroll
        for (int ks = 0; ks < 8; ks++) {
            uint32_t A[4][4];
#pragma unroll
            for (int mt = 0; mt < 4; mt++) {
                int arow = mt * 16 + a_row_off;
                int kc = ks * 2 + a_ksel;
                ldsm4(smem_base + OFF_A + (uint32_t)(arow * 256 + ((kc ^ (arow & 7)) << 4)), A[mt]);
            }
#pragma unroll
            for (int g2 = 0; g2 < 2; g2++) {
                int n = ng * 32 + g2 * 16 + b_n_off;     // buffer-local row
                int kc = ks * 2 + b_ksel;
                uint32_t Bhi[4];
                ldsm4(smem_base + OFF_W + (uint32_t)(n * 256 + ((kc ^ (n & 7)) << 4)), Bhi);
#pragma unroll
                for (int mt = 0; mt < 4; mt++) {
                    mma16816(acc[mt][g2 * 2],     A[mt], &Bhi[0]);
                    mma16816(acc[mt][g2 * 2 + 1], A[mt], &Bhi[2]);
                }
            }
        }
        __syncthreads();                        // all warps done reading right W
        load_whalf(smem_base, conv, 0, tid);    // prefetch left half (hidden by co-block)

        // right epilogue: rt[e][ng] (unique writer per warp — no atomics)
#pragma unroll
        for (int mt = 0; mt < 4; mt++)
#pragma unroll
            for (int h2 = 0; h2 < 2; h2++) {
                int e = mt * 16 + h2 * 8 + (lane >> 2);
                float s = 0.f;
#pragma unroll
                for (int nt = 0; nt < 4; nt++) {
                    int nc = nt * 8 + 2 * l4;
                    int o = 256 + ng * 32 + nc;
                    s += (acc[mt][nt][h2 * 2] + sh_bias[o]) * sh_t[e * 33 + nc]
                       + (acc[mt][nt][h2 * 2 + 1] + sh_bias[o + 1]) * sh_t[e * 33 + nc + 1];
                }
                s += __shfl_xor_sync(0xFFFFFFFFu, s, 1);
                s += __shfl_xor_sync(0xFFFFFFFFu, s, 2);
                if (l4 == 0) sh_rt[e * 8 + ng] = s;
            }
    }
    asm volatile("cp.async.wait_group 0;" ::: "memory");   // left W half resident
    __syncthreads();                                       // rt visible

    // ================= PASS L (W rows 0..255) =================
    {
        float acc[4][4][4];
#pragma unroll
        for (int mt = 0; mt < 4; mt++)
#pragma unroll
            for (int nt = 0; nt < 4; nt++)
#pragma unroll
                for (int u = 0; u < 4; u++) acc[mt][nt][u] = 0.f;
#pragma unroll
        for (int ks = 0; ks < 8; ks++) {
            uint32_t A[4][4];
#pragma unroll
            for (int mt = 0; mt < 4; mt++) {
                int arow = mt * 16 + a_row_off;
                int kc = ks * 2 + a_ksel;
                ldsm4(smem_base + OFF_A + (uint32_t)(arow * 256 + ((kc ^ (arow & 7)) << 4)), A[mt]);
            }
#pragma unroll
            for (int g2 = 0; g2 < 2; g2++) {
                int n = ng * 32 + g2 * 16 + b_n_off;
                int kc = ks * 2 + b_ksel;
                uint32_t Bhi[4];
                ldsm4(smem_base + OFF_W + (uint32_t)(n * 256 + ((kc ^ (n & 7)) << 4)), Bhi);
#pragma unroll
                for (int mt = 0; mt < 4; mt++) {
                    mma16816(acc[mt][g2 * 2],     A[mt], &Bhi[0]);
                    mma16816(acc[mt][g2 * 2 + 1], A[mt], &Bhi[2]);
                }
            }
        }
        // left epilogue: t2[e][ng*4+nt]
#pragma unroll
        for (int mt = 0; mt < 4; mt++)
#pragma unroll
            for (int h2 = 0; h2 < 2; h2++) {
                int e = mt * 16 + h2 * 8 + (lane >> 2);
                float r0 = sh_rt[e * 8 + 2 * l4];
                float r1 = sh_rt[e * 8 + 2 * l4 + 1];
#pragma unroll
                for (int nt = 0; nt < 4; nt++) {
                    int o = ng * 32 + nt * 8 + 2 * l4;
                    float s = (acc[mt][nt][h2 * 2] + sh_bias[o]) * r0
                            + (acc[mt][nt][h2 * 2 + 1] + sh_bias[o + 1]) * r1;
                    s += __shfl_xor_sync(0xFFFFFFFFu, s, 1);
                    s += __shfl_xor_sync(0xFFFFFFFFu, s, 2);
                    if (l4 == 0)
                        sh_t2[e * 33 + ng * 4 + nt] = s;
                }
            }
    }
    __syncthreads();

    // ---- final phase ----
    if (conv == 0) {
        // K: scores -> exp (no max pass; scores are O(1)) -> segment denominator
        int e = tid >> 2, hh = tid & 3;              // 256 = 64*4
        int dn = __ldg(&dst[e0 + e]);
        const float* qr = g_q + dn * 64 + hh * 16;
        float s = 0.f;
#pragma unroll
        for (int m = hh * 4; m < hh * 4 + 4; m++) {
            float ta = sh_t2[e * 33 + 2 * m];
            float tb = sh_t2[e * 33 + 2 * m + 1];
#pragma unroll
            for (int d = 0; d < 4; d++) {
                float kv = ta * basis2[(size_t)(e0 + e) * 8 + d]
                         + tb * basis2[(size_t)(e0 + e) * 8 + 4 + d];
                s += qr[(m - hh * 4) * 4 + d] * kv;
            }
        }
        float ex = expf(s * 0.25f);
        g_ex[(size_t)(e0 + e) * NH + hh] = ex;
        atomicAdd(&g_den[dn * NH + hh], ex);
    } else {
        // V: fused weighted scatter — alpha*v straight to dout via red.v4
        float* sh_alpha = sh_bias;                   // 256 floats (bias dead)
        int*   sh_dn    = (int*)(sm + OFF_RT);       // 64 ints (rt dead)
        {
            int e = tid >> 2, hh = tid & 3;
            int dn = __ldg(&dst[e0 + e]);
            if (hh == 0) sh_dn[e] = dn;
            float den = fmaxf(g_den[dn * NH + hh], 1e-9f);
            sh_alpha[tid] = g_ex[(size_t)(e0 + e) * NH + hh] / den;
        }
        __syncthreads();
#pragma unroll
        for (int r = 0; r < 4; r++) {
            int p = r * THREADS + tid;               // 1024 float4 groups
            int e = p >> 4, m = p & 15;
            int hh = m >> 2;
            float4 b2a = *reinterpret_cast<const float4*>(basis2 + (size_t)(e0 + e) * 8);
            float4 b2b = *reinterpret_cast<const float4*>(basis2 + (size_t)(e0 + e) * 8 + 4);
            float ta = sh_t2[e * 33 + 2 * m];
            float tb = sh_t2[e * 33 + 2 * m + 1];
            float al = sh_alpha[e * 4 + hh];
            float* op = dout + (size_t)sh_dn[e] * 64 + m * 4;
            asm volatile("red.global.add.v4.f32 [%0], {%1, %2, %3, %4};"
                         :: "l"(op),
                            "f"(al * (ta * b2a.x + tb * b2b.x)),
                            "f"(al * (ta * b2a.y + tb * b2b.y)),
                            "f"(al * (ta * b2a.z + tb * b2b.z)),
                            "f"(al * (ta * b2a.w + tb * b2b.w))
                         : "memory");
        }
    }
}

// ---------------- launch ----------------
extern "C" void kernel_launch(void* const* d_in, const int* in_sizes, int n_in,
                              void* d_out, int out_size) {
    const float* basis1 = (const float*)d_in[0];
    const float* basis2 = (const float*)d_in[1];
    const float* ef     = (const float*)d_in[2];
    const float* f      = (const float*)d_in[3];
    const int*   src    = (const int*)d_in[4];
    const int*   dst    = (const int*)d_in[5];
    const float* q_w    = (const float*)d_in[6];
    const float* q_b    = (const float*)d_in[7];
    const float* k_w1   = (const float*)d_in[8];
    const float* k_b1   = (const float*)d_in[9];
    const float* k_wl   = (const float*)d_in[10];
    const float* k_bl   = (const float*)d_in[11];
    const float* k_wr   = (const float*)d_in[12];
    const float* k_br   = (const float*)d_in[13];
    const float* v_w1   = (const float*)d_in[14];
    const float* v_b1   = (const float*)d_in[15];
    const float* v_wl   = (const float*)d_in[16];
    const float* v_bl   = (const float*)d_in[17];
    const float* v_wr   = (const float*)d_in[18];
    const float* v_br   = (const float*)d_in[19];
    float* dout = (float*)d_out;

    cudaFuncSetAttribute(conv_mma_kernel, cudaFuncAttributeMaxDynamicSharedMemorySize, SMEM_BYTES);

    presplit_kernel<<<512, 256>>>(k_wl, k_wr, v_wl, v_wr, k_bl, k_br, v_bl, v_br, k_w1, v_w1);
    qinit_kernel<<<(NN * 64 + 255) / 256, 256>>>(f, q_w, q_b, dout);
    conv_mma_kernel<<<EE / TM, THREADS, SMEM_BYTES>>>(
        basis1, basis2, ef, f, src, dst, k_b1, v_b1, dout, 0);   // K: scores + den
    conv_mma_kernel<<<EE / TM, THREADS, SMEM_BYTES>>>(
        basis1, basis2, ef, f, src, dst, k_b1, v_b1, dout, 1);   // V: fused scatter
}